// round 12
// baseline (speedup 1.0000x reference)
#include <cuda_runtime.h>
#include <cuda_fp16.h>
#include <cstdint>

#define Hd 1024
#define Fd 2048
#define Td 8192

// ---------------- scratch (__device__ globals; no allocs allowed) -------------
__device__ __align__(16) float g_wts[Td * 4];    // w0, w1, w2, w1+w2
__device__ __align__(16) float g_cvec[2][Fd];    // b_d @ ad_w1 + ad_b1
__device__ __align__(16) __half g_xp[(size_t)Td * Hd];      // packed norm(x)
__device__ __align__(16) __half g_Bp[2 * (size_t)Fd * Hd];  // packed W1^T scaled
__device__ __align__(16) __half g_W2p[(size_t)Hd * Fd];     // packed W2^T
__device__ __align__(16) __half g_gp[(size_t)Td * Fd];      // packed activation
__device__ int g_ctr;        // persistent work queue
__device__ int g_done[64];   // per-mb up-completion counters

#define N_UP 2048            // item = mb*32 + nb
#define N_DN 512             // item-2048 = mb*8 + hb
#define N_TOT (N_UP + N_DN)

// ---------------- PTX helpers -------------------------------------------------
__device__ __forceinline__ uint32_t smem_u32(const void* p) {
    uint32_t a;
    asm("{ .reg .u64 t; cvta.to.shared.u64 t, %1; cvt.u32.u64 %0, t; }"
        : "=r"(a) : "l"(p));
    return a;
}
#define LDSM4(r, a) \
    asm volatile("ldmatrix.sync.aligned.m8n8.x4.shared.b16 {%0,%1,%2,%3}, [%4];" \
                 : "=r"((r)[0]), "=r"((r)[1]), "=r"((r)[2]), "=r"((r)[3]) : "r"(a))
#define MBAR_INIT(a, c)  asm volatile("mbarrier.init.shared.b64 [%0], %1;" :: "r"(a), "r"((uint32_t)(c)) : "memory")
#define MBAR_EXPECT(a, tx) asm volatile("mbarrier.arrive.expect_tx.shared.b64 _, [%0], %1;" :: "r"(a), "r"((uint32_t)(tx)) : "memory")
#define MBAR_WAIT(a, p) do { \
    uint32_t _m = (a), _p = (uint32_t)(p), _d; \
    asm volatile("{\n\t.reg .pred q;\n\tmbarrier.try_wait.parity.acquire.cta.shared::cta.b64 q, [%1], %2;\n\tselp.b32 %0,1,0,q;\n\t}" \
                 : "=r"(_d) : "r"(_m), "r"(_p) : "memory"); \
    if (!_d) { \
        asm volatile("{\n\t.reg .pred q;\n\tLW_%=:\n\tmbarrier.try_wait.parity.acquire.cta.shared::cta.b64 q, [%0], %1, 0x989680;\n\t@q bra.uni LD_%=;\n\tbra.uni LW_%=;\n\tLD_%=:\n\t}" \
                     :: "r"(_m), "r"(_p) : "memory"); \
    } } while (0)
#define BULK(dst, src, sz, mb) \
    asm volatile("cp.async.bulk.shared::cluster.global.mbarrier::complete_tx::bytes [%0], [%1], %2, [%3];" \
                 :: "r"(dst), "l"(__cvta_generic_to_global(src)), "r"((uint32_t)(sz)), "r"(mb) : "memory")

__device__ __forceinline__ void mma_f16(float* d, const uint32_t* a,
                                        uint32_t b0, uint32_t b1) {
    asm volatile(
        "mma.sync.aligned.m16n8k16.row.col.f32.f16.f16.f32 "
        "{%0,%1,%2,%3}, {%4,%5,%6,%7}, {%8,%9}, {%0,%1,%2,%3};"
        : "+f"(d[0]), "+f"(d[1]), "+f"(d[2]), "+f"(d[3])
        : "r"(a[0]), "r"(a[1]), "r"(a[2]), "r"(a[3]), "r"(b0), "r"(b1));
}

__device__ __forceinline__ uint32_t hpack(float a, float b) {
    const __half2 h = __floats2half2_rn(a, b);
    return *(const uint32_t*)&h;
}
__device__ __forceinline__ size_t gp_off(int m, int f) {   // halves offset in g_gp
    return ((size_t)((m >> 7) * 64 + (f >> 5))) * 4096 +
           ((f >> 3) & 3) * 1024 + (m & 127) * 8 + (f & 7);
}

// ---------------- fused prep: trans1 | trans2 | prepc | gate ------------------
// block ranges: [0,2048) trans1, [2048,4096) trans2, [4096,4224) prepc,
//               [4224,5248) gate. All 256 threads.
__global__ void k_prep(const float* __restrict__ x, const int* __restrict__ dm,
                       const float* __restrict__ gw1, const float* __restrict__ gb1,
                       const float* __restrict__ gw2, const float* __restrict__ gb2,
                       const float* __restrict__ sb, const float* __restrict__ si,
                       const float* __restrict__ bb, const float* __restrict__ bi,
                       const float* __restrict__ aw1, const float* __restrict__ ab1,
                       const float* __restrict__ aw2) {
    __shared__ float sh[32 * 33];
    const int b = blockIdx.x;
    const int tid = threadIdx.x;

    if (b < 2048) {                    // ---- trans1: W1 -> packed, 2 domains
        const int tx = tid & 31, ty = tid >> 5;
        const int f0 = (b & 63) * 32, h0 = (b >> 6) * 32;
        #pragma unroll
        for (int i = 0; i < 4; i++) {
            const int h = h0 + ty + i * 8;
            sh[(ty + i * 8) * 33 + tx] = aw1[(size_t)h * Fd + f0 + tx];
        }
        __syncthreads();
        const int dom = tid >> 7, idx = tid & 127;
        const int hg = idx >> 5, fl = idx & 31;
        const int fo = f0 + fl;
        const float* sv = dom ? si : sb;
        uint32_t pk[4];
        #pragma unroll
        for (int q = 0; q < 4; q++) {
            const int hq = hg * 8 + 2 * q;
            const float v0 = sh[hq * 33 + fl] * __ldg(sv + h0 + hq);
            const float v1 = sh[(hq + 1) * 33 + fl] * __ldg(sv + h0 + hq + 1);
            pk[q] = hpack(v0, v1);
        }
        const int c = h0 >> 5;
        const size_t off = ((size_t)((fo >> 6) * 32 + c)) * 2048 +
                           hg * 512 + (fo & 63) * 8;
        *(uint4*)(g_Bp + (size_t)dom * Fd * Hd + off) = *(uint4*)pk;
    } else if (b < 4096) {             // ---- trans2: W2 -> packed
        const int bb2 = b - 2048;
        const int tx = tid & 31, ty = tid >> 5;
        const int h0 = (bb2 & 31) * 32, f0 = (bb2 >> 5) * 32;
        #pragma unroll
        for (int i = 0; i < 4; i++) {
            const int f = f0 + ty + i * 8;
            sh[(ty + i * 8) * 33 + tx] = aw2[(size_t)f * Hd + h0 + tx];
        }
        __syncthreads();
        if (tid < 128) {
            const int fg = tid >> 5, hl = tid & 31;
            const int ho = h0 + hl;
            uint32_t pk[4];
            #pragma unroll
            for (int q = 0; q < 4; q++) {
                const int fq = fg * 8 + 2 * q;
                pk[q] = hpack(sh[fq * 33 + hl], sh[(fq + 1) * 33 + hl]);
            }
            const int c = f0 >> 5;
            const size_t off = ((size_t)((ho >> 7) * 64 + c)) * 4096 +
                               fg * 1024 + (ho & 127) * 8;
            *(uint4*)(g_W2p + off) = *(uint4*)pk;
        }
    } else if (b < 4224) {             // ---- prepc + counter reset
        if (b == 4096 && tid < 96) {
            if (tid < 64) g_done[tid] = 0;
            else if (tid == 64) g_ctr = 0;
        }
        const int lane32 = tid & 31;
        const int ks = tid >> 5;
        const int i = (b - 4096) * 32 + lane32;
        const int d = i >> 11;
        const int f = i & (Fd - 1);
        const float* bv = d ? bi : bb;
        float acc = 0.f;
        #pragma unroll 8
        for (int h = ks * 128; h < ks * 128 + 128; h++)
            acc = fmaf(__ldg(bv + h), aw1[(size_t)h * Fd + f], acc);
        sh[ks * 32 + lane32] = acc;
        __syncthreads();
        if (ks == 0) {
            float s = sh[lane32];
            #pragma unroll
            for (int q = 1; q < 8; q++) s += sh[q * 32 + lane32];
            g_cvec[d][f] = ab1[f] + s;
        }
    } else {                           // ---- gate: LN stats + weights + xp
        const int t = (b - 4224) * 8 + (tid >> 5);
        const int lane = tid & 31;
        const float* xr = x + (size_t)t * Hd;

        float4 xv[8];
        float s = 0.f, ss = 0.f, a0 = 0.f, a1 = 0.f, a2 = 0.f, a3 = 0.f;
        #pragma unroll
        for (int it = 0; it < 4; it++) {
            const int h = lane * 8 + it * 256;
            xv[2 * it] = *(const float4*)(xr + h);
            xv[2 * it + 1] = *(const float4*)(xr + h + 4);
            const float* vv = (const float*)&xv[2 * it];
            const float4* gw = (const float4*)(gw1 + h * 4);
            #pragma unroll
            for (int q = 0; q < 8; q++) {
                const float v = vv[q];
                s += v; ss += v * v;
                const float4 wr = gw[q];
                a0 += v * wr.x; a1 += v * wr.y; a2 += v * wr.z; a3 += v * wr.w;
            }
        }
        #pragma unroll
        for (int o = 16; o; o >>= 1) {
            s  += __shfl_xor_sync(0xffffffffu, s, o);
            ss += __shfl_xor_sync(0xffffffffu, ss, o);
            a0 += __shfl_xor_sync(0xffffffffu, a0, o);
            a1 += __shfl_xor_sync(0xffffffffu, a1, o);
            a2 += __shfl_xor_sync(0xffffffffu, a2, o);
            a3 += __shfl_xor_sync(0xffffffffu, a3, o);
        }
        const float mean = s * (1.f / Hd);
        const float var = ss * (1.f / Hd) - mean * mean;
        const float rstd = rsqrtf(var + 1e-6f);

        const int mb = t >> 7, r = t & 127;
        #pragma unroll
        for (int it = 0; it < 4; it++) {
            const int h = lane * 8 + it * 256;
            const int c = h >> 5, kb = (h >> 3) & 3;
            const float* vv = (const float*)&xv[2 * it];
            uint4 o;
            o.x = hpack((vv[0] - mean) * rstd, (vv[1] - mean) * rstd);
            o.y = hpack((vv[2] - mean) * rstd, (vv[3] - mean) * rstd);
            o.z = hpack((vv[4] - mean) * rstd, (vv[5] - mean) * rstd);
            o.w = hpack((vv[6] - mean) * rstd, (vv[7] - mean) * rstd);
            *(uint4*)(g_xp + ((size_t)(mb * 32 + c)) * 4096 + kb * 1024 + r * 8) = o;
        }

        if (lane == 0) {
            float hv[4] = {fmaxf(a0 + gb1[0], 0.f), fmaxf(a1 + gb1[1], 0.f),
                           fmaxf(a2 + gb1[2], 0.f), fmaxf(a3 + gb1[3], 0.f)};
            float lg[4];
            #pragma unroll
            for (int e = 0; e < 4; e++) {
                float acc = gb2[e];
                #pragma unroll
                for (int d = 0; d < 4; d++) acc += hv[d] * gw2[d * 4 + e];
                if (dm[e] == 0) acc = -1e9f;
                lg[e] = acc;
            }
            const float mx = fmaxf(fmaxf(lg[0], lg[1]), fmaxf(lg[2], lg[3]));
            const float e0 = expf(lg[0] - mx), e1 = expf(lg[1] - mx);
            const float e2 = expf(lg[2] - mx), e3 = expf(lg[3] - mx);
            const float inv = 1.f / (e0 + e1 + e2 + e3);
            g_wts[4 * t + 0] = e0 * inv;
            g_wts[4 * t + 1] = e1 * inv;
            g_wts[4 * t + 2] = e2 * inv;
            g_wts[4 * t + 3] = (e1 + e2) * inv;
        }
    }
}

// ---------------- persistent fused GEMM: up queue then down queue -------------
// 3x32KB TMA ring persists across items (stage = N%3, parity = (N/3)&1).
#define GM_SMEM  98368
#define GM_STAGE 32768
__global__ void __launch_bounds__(128, 2) k_gemm(const float* __restrict__ x,
                                                 const float* __restrict__ b2,
                                                 float* __restrict__ out) {
    extern __shared__ char smem[];
    __shared__ int s_item;
    const uint32_t sm = smem_u32(smem);
    const uint32_t mbb = sm + 98304;
    const int tid = threadIdx.x, lane = tid & 31, wid = tid >> 5;
    const int aRow = lane & 15, aK = lane >> 4;
    const int bRow = (lane & 7) + ((lane >> 4) << 3), bK = (lane >> 3) & 1;

    if (tid == 0) {
        #pragma unroll
        for (int st = 0; st < 3; st++) MBAR_INIT(mbb + st * 8, 1);
    }
    __syncthreads();

    int Nf = 0, Nc = 0;

    for (;;) {
        if (tid == 0) s_item = atomicAdd(&g_ctr, 1);
        __syncthreads();
        const int item = s_item;
        if (item >= N_TOT) break;

        float acc[4][8][4];
        #pragma unroll
        for (int i = 0; i < 4; i++)
            #pragma unroll
            for (int n = 0; n < 8; n++)
                #pragma unroll
                for (int q = 0; q < 4; q++) acc[i][n][q] = 0.f;

        if (item < N_UP) {
            // ================= UP tile: 128m x 64f x 2dom ====================
            const int mb = item >> 5, nb = item & 31;
            const int m0 = mb * 128, n0 = nb * 64;
            const int dom = wid >> 1, mw = (wid & 1) * 64;

            auto issue = [&](int c, int st) {
                const uint32_t mbar = mbb + st * 8;
                const uint32_t dst = sm + st * GM_STAGE;
                MBAR_EXPECT(mbar, 32768);
                BULK(dst, g_xp + ((size_t)(mb * 32 + c * 2)) * 4096, 16384, mbar);
                BULK(dst + 16384, g_Bp + ((size_t)(nb * 32 + c * 2)) * 2048, 8192, mbar);
                BULK(dst + 24576, g_Bp + (size_t)Fd * Hd + ((size_t)(nb * 32 + c * 2)) * 2048, 8192, mbar);
            };

            if (tid == 0) { issue(0, Nf % 3); issue(1, (Nf + 1) % 3); }
            int NfL = Nf + 2;

            #pragma unroll 1
            for (int c = 0; c < 16; c++) {
                __syncthreads();
                if (c + 2 < 16) {
                    if (tid == 0) issue(c + 2, NfL % 3);
                    NfL++;
                }
                const int stC = Nc % 3, pc = (Nc / 3) & 1;
                Nc++;
                MBAR_WAIT(mbb + stC * 8, pc);
                const uint32_t smA = sm + stC * GM_STAGE;
                const uint32_t smB = smA + 16384 + dom * 8192;
                #pragma unroll
                for (int j = 0; j < 4; j++) {
                    uint32_t a[4][4];
                    const uint32_t aBase = smA + (j >> 1) * 8192 +
                        (((2 * (j & 1) + aK) << 7) + mw + aRow) * 16;
                    #pragma unroll
                    for (int i = 0; i < 4; i++) LDSM4(a[i], aBase + i * 256);
                    uint32_t bb[4][4];
                    const uint32_t bBase = smB + (j >> 1) * 4096 +
                        (((2 * (j & 1) + bK) << 6) + bRow) * 16;
                    #pragma unroll
                    for (int nb2 = 0; nb2 < 4; nb2++) LDSM4(bb[nb2], bBase + nb2 * 256);
                    #pragma unroll
                    for (int i = 0; i < 4; i++)
                        #pragma unroll
                        for (int nb2 = 0; nb2 < 4; nb2++) {
                            mma_f16(acc[i][2 * nb2 + 0], a[i], bb[nb2][0], bb[nb2][1]);
                            mma_f16(acc[i][2 * nb2 + 1], a[i], bb[nb2][2], bb[nb2][3]);
                        }
                }
            }
            Nf = NfL;

            // epilogue: dom1 -> smem (w2*relu), dom0 combines, writes packed g
            __syncthreads();
            const int g = lane >> 2, tq = lane & 3;
            float* ex = (float*)smem;               // [128][68] f32
            if (dom == 1) {
                #pragma unroll
                for (int i = 0; i < 4; i++) {
                    const int r = mw + 16 * i + g;
                    const float w2a = g_wts[4 * (m0 + r) + 2];
                    const float w2b = g_wts[4 * (m0 + r + 8) + 2];
                    #pragma unroll
                    for (int n = 0; n < 8; n++) {
                        const int col = 8 * n + 2 * tq;
                        const float cv0 = g_cvec[1][n0 + col], cv1 = g_cvec[1][n0 + col + 1];
                        float2 v0, v1;
                        v0.x = w2a * fmaxf(acc[i][n][0] + cv0, 0.f);
                        v0.y = w2a * fmaxf(acc[i][n][1] + cv1, 0.f);
                        v1.x = w2b * fmaxf(acc[i][n][2] + cv0, 0.f);
                        v1.y = w2b * fmaxf(acc[i][n][3] + cv1, 0.f);
                        *(float2*)(ex + (size_t)r * 68 + col) = v0;
                        *(float2*)(ex + (size_t)(r + 8) * 68 + col) = v1;
                    }
                }
            }
            __syncthreads();
            if (dom == 0) {
                #pragma unroll
                for (int i = 0; i < 4; i++) {
                    const int r = mw + 16 * i + g;
                    const float w1a = g_wts[4 * (m0 + r) + 1];
                    const float w1b = g_wts[4 * (m0 + r + 8) + 1];
                    #pragma unroll
                    for (int n = 0; n < 8; n++) {
                        const int col = 8 * n + 2 * tq;
                        const int fg = n0 + col;
                        const float cv0 = g_cvec[0][fg], cv1 = g_cvec[0][fg + 1];
                        const float2 s0 = *(const float2*)(ex + (size_t)r * 68 + col);
                        const float2 s1 = *(const float2*)(ex + (size_t)(r + 8) * 68 + col);
                        const float g0 = w1a * fmaxf(acc[i][n][0] + cv0, 0.f) + s0.x;
                        const float g1 = w1a * fmaxf(acc[i][n][1] + cv1, 0.f) + s0.y;
                        const float g2 = w1b * fmaxf(acc[i][n][2] + cv0, 0.f) + s1.x;
                        const float g3 = w1b * fmaxf(acc[i][n][3] + cv1, 0.f) + s1.y;
                        *(uint32_t*)(g_gp + gp_off(m0 + r, fg)) = hpack(g0, g1);
                        *(uint32_t*)(g_gp + gp_off(m0 + r + 8, fg)) = hpack(g2, g3);
                    }
                }
            }
            __threadfence();
            __syncthreads();
            if (tid == 0) atomicAdd(&g_done[mb], 1);
        } else {
            // ================= DOWN tile: 128m x 128h ========================
            const int it2 = item - N_UP;
            const int mb = it2 >> 3, hb = it2 & 7;
            const int m0 = mb * 128, n0 = hb * 128;
            const int mw = (wid & 1) * 64, nw = (wid >> 1) * 64;

            if (tid == 0) {
                while (atomicAdd(&g_done[mb], 0) < 32) { }
                __threadfence();
            }
            __syncthreads();

            auto issue = [&](int c, int st) {
                const uint32_t mbar = mbb + st * 8;
                const uint32_t dst = sm + st * GM_STAGE;
                MBAR_EXPECT(mbar, 32768);
                BULK(dst, g_gp + ((size_t)(mb * 64 + c * 2)) * 4096, 16384, mbar);
                BULK(dst + 16384, g_W2p + ((size_t)(hb * 64 + c * 2)) * 4096, 16384, mbar);
            };

            if (tid == 0) { issue(0, Nf % 3); issue(1, (Nf + 1) % 3); }
            int NfL = Nf + 2;

            #pragma unroll 1
            for (int c = 0; c < 32; c++) {
                __syncthreads();
                if (c + 2 < 32) {
                    if (tid == 0) issue(c + 2, NfL % 3);
                    NfL++;
                }
                const int stC = Nc % 3, pc = (Nc / 3) & 1;
                Nc++;
                MBAR_WAIT(mbb + stC * 8, pc);
                const uint32_t smA = sm + stC * GM_STAGE;
                const uint32_t smB = smA + 16384;
                #pragma unroll
                for (int j = 0; j < 4; j++) {
                    uint32_t a[4][4];
                    const uint32_t aBase = smA + (j >> 1) * 8192 +
                        (((2 * (j & 1) + aK) << 7) + mw + aRow) * 16;
                    #pragma unroll
                    for (int i = 0; i < 4; i++) LDSM4(a[i], aBase + i * 256);
                    uint32_t bb[4][4];
                    const uint32_t bBase = smB + (j >> 1) * 8192 +
                        (((2 * (j & 1) + bK) << 7) + nw + bRow) * 16;
                    #pragma unroll
                    for (int nb2 = 0; nb2 < 4; nb2++) LDSM4(bb[nb2], bBase + nb2 * 256);
                    #pragma unroll
                    for (int i = 0; i < 4; i++)
                        #pragma unroll
                        for (int nb2 = 0; nb2 < 4; nb2++) {
                            mma_f16(acc[i][2 * nb2 + 0], a[i], bb[nb2][0], bb[nb2][1]);
                            mma_f16(acc[i][2 * nb2 + 1], a[i], bb[nb2][2], bb[nb2][3]);
                        }
                }
            }
            Nf = NfL;

            // epilogue: out = x*(1+w0) + acc + (w1+w2)*b2
            const int g = lane >> 2, tq = lane & 3;
            #pragma unroll
            for (int i = 0; i < 4; i++) {
                const int r0 = m0 + mw + 16 * i + g;
                const float4 wv0 = *(const float4*)&g_wts[4 * r0];
                const float4 wv1 = *(const float4*)&g_wts[4 * (r0 + 8)];
                const float xs0 = 1.f + wv0.x, w120 = wv0.w;
                const float xs1 = 1.f + wv1.x, w121 = wv1.w;
                #pragma unroll
                for (int n = 0; n < 8; n++) {
                    const int h = n0 + nw + 8 * n + 2 * tq;
                    const float2 xa = *(const float2*)&x[(size_t)r0 * Hd + h];
                    const float2 xb = *(const float2*)&x[(size_t)(r0 + 8) * Hd + h];
                    const float2 bv = *(const float2*)&b2[h];
                    float2 o0, o1;
                    o0.x = xa.x * xs0 + acc[i][n][0] + w120 * bv.x;
                    o0.y = xa.y * xs0 + acc[i][n][1] + w120 * bv.y;
                    o1.x = xb.x * xs1 + acc[i][n][2] + w121 * bv.x;
                    o1.y = xb.y * xs1 + acc[i][n][3] + w121 * bv.y;
                    *(float2*)&out[(size_t)r0 * Hd + h] = o0;
                    *(float2*)&out[(size_t)(r0 + 8) * Hd + h] = o1;
                }
            }
            __syncthreads();   // protect s_item + stage reuse for next item
        }
    }
}

// ---------------- launch ------------------------------------------------------
extern "C" void kernel_launch(void* const* d_in, const int* in_sizes, int n_in,
                              void* d_out, int out_size) {
    const float* x   = (const float*)d_in[0];
    const int*   dm  = (const int*)d_in[1];
    const float* gw1 = (const float*)d_in[2];
    const float* gb1 = (const float*)d_in[3];
    const float* gw2 = (const float*)d_in[4];
    const float* gb2 = (const float*)d_in[5];
    const float* sb  = (const float*)d_in[6];
    const float* bb  = (const float*)d_in[7];
    const float* si  = (const float*)d_in[8];
    const float* bi  = (const float*)d_in[9];
    const float* aw1 = (const float*)d_in[10];
    const float* ab1 = (const float*)d_in[11];
    const float* aw2 = (const float*)d_in[12];
    const float* ab2 = (const float*)d_in[13];
    float* out = (float*)d_out;

    cudaFuncSetAttribute(k_gemm, cudaFuncAttributeMaxDynamicSharedMemorySize, GM_SMEM);

    k_prep<<<5248, 256>>>(x, dm, gw1, gb1, gw2, gb2, sb, si, bb, bi, aw1, ab1, aw2);
    k_gemm<<<304, 128, GM_SMEM>>>(x, ab2, out);
}